// round 5
// baseline (speedup 1.0000x reference)
#include <cuda_runtime.h>
#include <cuda_bf16.h>
#include <cstdint>

// ============================================================================
// PoolBondFeatures, round 5 (no tcgen05 on plain sm_100 target -> HMMA):
//   Phase 1 (fp32 FFMA2, per NODE):  AB[n] = h[n] @ [W1a | W1b] (+b1 in A half)
//   Phase 2 (persistent, warp-level mma.sync split-bf16, 64-edge tiles):
//       S[e] = relu(A[s]+B[d]) + relu(A[d]+B[s])        (fp32, L2-resident)
//       S = Shi + Slo; W2 = W2hi + W2lo (precomputed)
//       D  = Shi@W2hi + Shi@W2lo + Slo@W2hi              (fp32 accum in regs)
//       out[e] = D + 2*b2
// ============================================================================

#define D128 128
#define MAX_N 65536

__device__ float g_AB[(size_t)MAX_N * 256];
// W2^T as [n][k] bf16, plain row-major (k contiguous), hi/lo split.
__device__ __align__(16) unsigned char g_W2hi[32768];
__device__ __align__(16) unsigned char g_W2lo[32768];

// ---------------------------------------------------------------- helpers
__device__ __forceinline__ uint32_t smem_u32(const void* p) {
    uint32_t a;
    asm("{ .reg .u64 t; cvta.to.shared.u64 t, %1; cvt.u32.u64 %0, t; }"
        : "=r"(a) : "l"(p));
    return a;
}
__device__ __forceinline__ void ldsm_x4(uint32_t* r, uint32_t addr) {
    asm volatile("ldmatrix.sync.aligned.m8n8.x4.shared.b16 {%0,%1,%2,%3}, [%4];"
                 : "=r"(r[0]), "=r"(r[1]), "=r"(r[2]), "=r"(r[3]) : "r"(addr));
}
__device__ __forceinline__ void mma16816(float* c, const uint32_t* a,
                                         const uint32_t* b) {
    asm volatile(
        "mma.sync.aligned.m16n8k16.row.col.f32.bf16.bf16.f32 "
        "{%0,%1,%2,%3}, {%4,%5,%6,%7}, {%8,%9}, {%0,%1,%2,%3};"
        : "+f"(c[0]), "+f"(c[1]), "+f"(c[2]), "+f"(c[3])
        : "r"(a[0]), "r"(a[1]), "r"(a[2]), "r"(a[3]), "r"(b[0]), "r"(b[1]));
}

__device__ __forceinline__ unsigned long long pack2(float lo, float hi) {
    unsigned long long r;
    asm("mov.b64 %0, {%1, %2};" : "=l"(r) : "f"(lo), "f"(hi));
    return r;
}
__device__ __forceinline__ unsigned long long ffma2(unsigned long long a,
                                                    unsigned long long b,
                                                    unsigned long long c) {
    unsigned long long d;
    asm("fma.rn.f32x2 %0, %1, %2, %3;" : "=l"(d) : "l"(a), "l"(b), "l"(c));
    return d;
}

// ----------------------------------------------------------------------------
// Phase 1: AB[row] = h[row] @ [W1a|W1b] (+b1)   (fp32 FFMA2 GEMM)
// ----------------------------------------------------------------------------
__global__ void __launch_bounds__(256, 2) phase1_kernel(
    const float* __restrict__ h, const float* __restrict__ W1,
    const float* __restrict__ b1, int N)
{
    __shared__ __align__(16) float hs[64 * 32];
    __shared__ __align__(16) float Ws[32 * 256];

    const int tid = threadIdx.x;
    const int tx = tid & 31;
    const int ty = tid >> 5;
    const int row0 = blockIdx.x * 64;

    unsigned long long acc[8][4];
    {
        float4 bv = *(const float4*)&b1[4 * tx];
        #pragma unroll
        for (int i = 0; i < 8; i++) {
            acc[i][0] = pack2(bv.x, bv.y);
            acc[i][1] = pack2(bv.z, bv.w);
            acc[i][2] = 0ULL;
            acc[i][3] = 0ULL;
        }
    }

    for (int k0 = 0; k0 < 128; k0 += 32) {
        #pragma unroll
        for (int it = 0; it < 2; it++) {
            int idx4 = tid + it * 256;
            int r = idx4 >> 3;
            int kq = idx4 & 7;
            int row = row0 + r;
            if (row > N - 1) row = N - 1;
            *(float4*)&hs[r * 32 + kq * 4] =
                *(const float4*)&h[(size_t)row * D128 + k0 + kq * 4];
        }
        #pragma unroll
        for (int it = 0; it < 8; it++) {
            int idx4 = tid + it * 256;
            int lin = idx4 * 4;
            int k = lin >> 8;
            int jp = lin & 255;
            const float* sw = (jp < 128)
                ? (W1 + (size_t)(k0 + k) * D128 + jp)
                : (W1 + (size_t)(128 + k0 + k) * D128 + (jp - 128));
            *(float4*)&Ws[k * 256 + jp] = *(const float4*)sw;
        }
        __syncthreads();

        #pragma unroll
        for (int kk = 0; kk < 32; kk += 2) {
            ulonglong2 w00 = *(const ulonglong2*)&Ws[kk * 256 + 4 * tx];
            ulonglong2 w01 = *(const ulonglong2*)&Ws[kk * 256 + 128 + 4 * tx];
            ulonglong2 w10 = *(const ulonglong2*)&Ws[(kk + 1) * 256 + 4 * tx];
            ulonglong2 w11 = *(const ulonglong2*)&Ws[(kk + 1) * 256 + 128 + 4 * tx];
            #pragma unroll
            for (int i = 0; i < 8; i++) {
                float2 a = *(const float2*)&hs[(ty * 8 + i) * 32 + kk];
                unsigned long long a0 = pack2(a.x, a.x);
                acc[i][0] = ffma2(a0, w00.x, acc[i][0]);
                acc[i][1] = ffma2(a0, w00.y, acc[i][1]);
                acc[i][2] = ffma2(a0, w01.x, acc[i][2]);
                acc[i][3] = ffma2(a0, w01.y, acc[i][3]);
                unsigned long long a1 = pack2(a.y, a.y);
                acc[i][0] = ffma2(a1, w10.x, acc[i][0]);
                acc[i][1] = ffma2(a1, w10.y, acc[i][1]);
                acc[i][2] = ffma2(a1, w11.x, acc[i][2]);
                acc[i][3] = ffma2(a1, w11.y, acc[i][3]);
            }
        }
        __syncthreads();
    }

    #pragma unroll
    for (int i = 0; i < 8; i++) {
        int row = row0 + ty * 8 + i;
        if (row < N) {
            ulonglong2 v0; v0.x = acc[i][0]; v0.y = acc[i][1];
            *(ulonglong2*)&g_AB[(size_t)row * 256 + 4 * tx] = v0;
            ulonglong2 v1; v1.x = acc[i][2]; v1.y = acc[i][3];
            *(ulonglong2*)&g_AB[(size_t)row * 256 + 128 + 4 * tx] = v1;
        }
    }
}

// ----------------------------------------------------------------------------
// W2 prep: g_W2hi/lo[n][k] = split(W2[k][n]), plain [128][128] bf16 row-major.
// ----------------------------------------------------------------------------
__global__ void w2prep_kernel(const float* __restrict__ W2) {
    int i = blockIdx.x * blockDim.x + threadIdx.x;   // 0..16383
    int n = i >> 7, k = i & 127;
    float w = W2[(size_t)k * 128 + n];
    __nv_bfloat16 hi = __float2bfloat16_rn(w);
    __nv_bfloat16 lo = __float2bfloat16_rn(w - __bfloat162float(hi));
    ((__nv_bfloat16*)g_W2hi)[n * 128 + k] = hi;
    ((__nv_bfloat16*)g_W2lo)[n * 128 + k] = lo;
}

// ----------------------------------------------------------------------------
// Phase 2: persistent CTAs, 64-edge tiles, split-bf16 HMMA
// SMEM layout (bytes, pitch = 136 bf16 = 272 B per row):
// ----------------------------------------------------------------------------
static constexpr uint32_t PITCHB  = 272;           // bytes per row
static constexpr uint32_t OFF_SHI = 0;             // 64*272 = 17408
static constexpr uint32_t OFF_SLO = 17408;
static constexpr uint32_t OFF_WHI = 34816;         // 128*272 = 34816
static constexpr uint32_t OFF_WLO = 69632;
static constexpr uint32_t OFF_B2  = 104448;        // 128 floats
static constexpr uint32_t SMEM_SZ = 104960;

__device__ __forceinline__ void split_pack(float a, float b, uint32_t& hi, uint32_t& lo) {
    __nv_bfloat16 ha = __float2bfloat16_rn(a);
    __nv_bfloat16 hb = __float2bfloat16_rn(b);
    __nv_bfloat16 la = __float2bfloat16_rn(a - __bfloat162float(ha));
    __nv_bfloat16 lb = __float2bfloat16_rn(b - __bfloat162float(hb));
    __nv_bfloat162 hv; hv.x = ha; hv.y = hb;
    __nv_bfloat162 lv; lv.x = la; lv.y = lb;
    hi = *(uint32_t*)&hv;
    lo = *(uint32_t*)&lv;
}

__global__ void __launch_bounds__(256, 2) phase2_mma_kernel(
    const void* __restrict__ srcp, const void* __restrict__ dstp,
    const float* __restrict__ b2, float* __restrict__ out, int E, int ntiles)
{
    extern __shared__ __align__(16) unsigned char smem[];
    const uint32_t sbase = smem_u32(smem);
    float* b2s = (float*)(smem + OFF_B2);
    const int tid = threadIdx.x;
    const int wid = tid >> 5, lid = tid & 31;

    // W2 hi/lo -> padded SMEM (rows n=0..127, 16 segs of 16B each)
    for (int i = tid; i < 128 * 16; i += 256) {
        int row = i >> 4, seg = i & 15;
        *(uint4*)(smem + OFF_WHI + row * PITCHB + seg * 16) =
            *(const uint4*)(g_W2hi + row * 256 + seg * 16);
        *(uint4*)(smem + OFF_WLO + row * PITCHB + seg * 16) =
            *(const uint4*)(g_W2lo + row * 256 + seg * 16);
    }
    if (tid < 128) b2s[tid] = 2.f * b2[tid];

    // index dtype sniff (declared int64; may really be int32 on device)
    const long long* s64 = (const long long*)srcp;
    const int* s32 = (const int*)srcp;
    const long long* d64 = (const long long*)dstp;
    const int* d32 = (const int*)dstp;
    unsigned long long mbits = (unsigned long long)(s64[0] | s64[1] | s64[2] | s64[3]);
    const bool idx64 = (mbits >> 31) == 0ULL;
    __syncthreads();

    // warp tiling: 2 M-groups x 4 N-groups; warp = 32 edges x 32 cols
    const int mg = wid >> 2;        // 0..1
    const int ng = wid & 3;         // 0..3

    // ldmatrix lane address components
    const int a_row  = (lid & 7) + ((lid >> 3) & 1) * 8;   // 0..15
    const int a_koff = (lid >> 4) * 16;                    // bytes
    const int b_n    = (lid & 7) + ((lid >> 4) & 1) * 8;   // 0..15
    const int b_koff = ((lid >> 3) & 1) * 16;              // bytes

    // gather assignment: edge eloc = tid>>2, col quarter c0 = (tid&3)*32
    const int eloc = tid >> 2;
    const int gc0 = (tid & 3) * 32;

    for (int t = blockIdx.x; t < ntiles; t += gridDim.x) {
        const int tile0 = t * 64;

        // ---- gather + relu-sum + bf16 split into S hi/lo ----
        {
            int e = tile0 + eloc;
            if (e >= E) e = E - 1;
            const int si = idx64 ? (int)s64[e] : s32[e];
            const int di = idx64 ? (int)d64[e] : d32[e];
            const float* As = g_AB + (size_t)si * 256 + gc0;
            const float* Bs = As + 128;
            const float* Ad = g_AB + (size_t)di * 256 + gc0;
            const float* Bd = Ad + 128;
            unsigned char* shi = smem + OFF_SHI + (uint32_t)eloc * PITCHB + gc0 * 2;
            unsigned char* slo = smem + OFF_SLO + (uint32_t)eloc * PITCHB + gc0 * 2;
            #pragma unroll
            for (int j = 0; j < 32; j += 4) {
                float4 as = *(const float4*)(As + j);
                float4 bd = *(const float4*)(Bd + j);
                float4 ad = *(const float4*)(Ad + j);
                float4 bs = *(const float4*)(Bs + j);
                float4 r;
                r.x = fmaxf(as.x + bd.x, 0.f) + fmaxf(ad.x + bs.x, 0.f);
                r.y = fmaxf(as.y + bd.y, 0.f) + fmaxf(ad.y + bs.y, 0.f);
                r.z = fmaxf(as.z + bd.z, 0.f) + fmaxf(ad.z + bs.z, 0.f);
                r.w = fmaxf(as.w + bd.w, 0.f) + fmaxf(ad.w + bs.w, 0.f);
                uint2 hp, lp;
                split_pack(r.x, r.y, hp.x, lp.x);
                split_pack(r.z, r.w, hp.y, lp.y);
                *(uint2*)(shi + j * 2) = hp;
                *(uint2*)(slo + j * 2) = lp;
            }
        }
        __syncthreads();

        // ---- GEMM: acc[2][4][4], K = 8 chunks of 16 ----
        float acc[2][4][4];
        #pragma unroll
        for (int mb = 0; mb < 2; mb++)
            #pragma unroll
            for (int nb = 0; nb < 4; nb++)
                #pragma unroll
                for (int i = 0; i < 4; i++) acc[mb][nb][i] = 0.f;

        #pragma unroll
        for (int kc = 0; kc < 8; kc++) {
            const uint32_t kbyte = (uint32_t)kc * 32;
            uint32_t Ahi[2][4], Alo[2][4];
            #pragma unroll
            for (int mb = 0; mb < 2; mb++) {
                uint32_t rrow = (uint32_t)(mg * 32 + mb * 16 + a_row);
                uint32_t ad = sbase + OFF_SHI + rrow * PITCHB + kbyte + a_koff;
                ldsm_x4(Ahi[mb], ad);
                ldsm_x4(Alo[mb], ad + (OFF_SLO - OFF_SHI));
            }
            uint32_t Bhi[4][2], Blo[4][2];
            #pragma unroll
            for (int p = 0; p < 2; p++) {
                uint32_t nrow = (uint32_t)(ng * 32 + p * 16 + b_n);
                uint32_t ad = sbase + OFF_WHI + nrow * PITCHB + kbyte + b_koff;
                uint32_t r[4];
                ldsm_x4(r, ad);
                Bhi[2 * p][0] = r[0]; Bhi[2 * p][1] = r[1];
                Bhi[2 * p + 1][0] = r[2]; Bhi[2 * p + 1][1] = r[3];
                ldsm_x4(r, ad + (OFF_WLO - OFF_WHI));
                Blo[2 * p][0] = r[0]; Blo[2 * p][1] = r[1];
                Blo[2 * p + 1][0] = r[2]; Blo[2 * p + 1][1] = r[3];
            }
            #pragma unroll
            for (int mb = 0; mb < 2; mb++)
                #pragma unroll
                for (int nb = 0; nb < 4; nb++) {
                    mma16816(acc[mb][nb], Ahi[mb], Bhi[nb]);
                    mma16816(acc[mb][nb], Ahi[mb], Blo[nb]);
                    mma16816(acc[mb][nb], Alo[mb], Bhi[nb]);
                }
        }
        __syncthreads();   // all warps done reading S before next gather

        // ---- epilogue: acc + 2*b2 -> out ----
        {
            const int gid = lid >> 2, tig = lid & 3;
            #pragma unroll
            for (int mb = 0; mb < 2; mb++) {
                const int e0 = tile0 + mg * 32 + mb * 16 + gid;
                const int e1 = e0 + 8;
                #pragma unroll
                for (int nb = 0; nb < 4; nb++) {
                    const int c = ng * 32 + nb * 8 + tig * 2;
                    float2 bb = *(const float2*)&b2s[c];
                    if (e0 < E) {
                        float2 v; v.x = acc[mb][nb][0] + bb.x;
                        v.y = acc[mb][nb][1] + bb.y;
                        *(float2*)&out[(size_t)e0 * D128 + c] = v;
                    }
                    if (e1 < E) {
                        float2 v; v.x = acc[mb][nb][2] + bb.x;
                        v.y = acc[mb][nb][3] + bb.y;
                        *(float2*)&out[(size_t)e1 * D128 + c] = v;
                    }
                }
            }
        }
    }
}

// ----------------------------------------------------------------------------
extern "C" void kernel_launch(void* const* d_in, const int* in_sizes, int n_in,
                              void* d_out, int out_size) {
    const float* h  = (const float*)d_in[0];
    const void*  sp = d_in[1];
    const void*  dp = d_in[2];
    const float* W1 = (const float*)d_in[3];
    const float* b1 = (const float*)d_in[4];
    const float* W2 = (const float*)d_in[5];
    const float* b2 = (const float*)d_in[6];
    float* out = (float*)d_out;

    int N = in_sizes[0] / D128;
    int E = in_sizes[1];
    if (N > MAX_N) N = MAX_N;

    cudaFuncSetAttribute(phase2_mma_kernel,
                         cudaFuncAttributeMaxDynamicSharedMemorySize, SMEM_SZ);

    w2prep_kernel<<<64, 256>>>(W2);

    int g1 = (N + 63) / 64;
    phase1_kernel<<<g1, 256>>>(h, W1, b1, N);

    int ntiles = (E + 63) / 64;
    int g2 = ntiles < 296 ? ntiles : 296;
    phase2_mma_kernel<<<g2, 256, SMEM_SZ>>>(sp, dp, b2, out, E, ntiles);

    (void)n_in; (void)out_size;
}